// round 4
// baseline (speedup 1.0000x reference)
#include <cuda_runtime.h>
#include <math.h>

// ---------------------------------------------------------------------------
// Problem constants
//  B=4096, SEQ=C=8, D=4, L=2048, NK=256, NCLS=100
//  filters: w3 (256,3,2048), w4 (256,4,2048), w5 (256,5,2048) -> 3072 rows
// ---------------------------------------------------------------------------

#define NKK 3072           // total filter rows (n*12 + kk), kk: 0-2 K3, 3-6 K4, 7-11 K5
#define NCLS 100

__device__ float g_WeF[5 * NKK];      // [d][nkk]; d=4 holds be-projection
__device__ float g_V[8 * 16 * NCLS];  // per (position h, code j) logit contribution
__device__ int   g_x64;               // 1 if x is int64, 0 if int32

// ---------------------------------------------------------------------------
// K1: WeF[d][nkk] = sum_l {We[d,:],be}[l] * w_row[nkk][l]
//     DRAM-bound 24 MB read. Warp-per-row, 256 thr/block (8 rows), grid 384.
//     Double-buffered batches of 8 independent LDG.128 per lane.
// ---------------------------------------------------------------------------
__global__ void __launch_bounds__(256, 1)
k1_wef(const float* __restrict__ We, const float* __restrict__ be,
       const float* __restrict__ w3, const float* __restrict__ w4,
       const float* __restrict__ w5, const void* __restrict__ xraw)
{
    __shared__ float4 sW4[5 * 512];   // [d][l/4]
    const int tid = threadIdx.x;

    if (blockIdx.x == 0 && tid == 0) {
        // int64 layout -> odd int32 words all zero (values in [0,1500))
        const int* xi = (const int*)xraw;
        int any = 0;
        #pragma unroll 1
        for (int i = 1; i < 256; i += 2) any |= xi[i];
        g_x64 = (any == 0) ? 1 : 0;
    }

    for (int gz = blockIdx.x * 256 + tid; gz < 8 * 16 * NCLS; gz += 384 * 256)
        g_V[gz] = 0.f;

    const int warp = tid >> 5, lane = tid & 31;
    const int rid = blockIdx.x * 8 + warp;   // one row per warp

    const float4* rp;
    {
        int n = rid / 12, kk = rid % 12;
        const float* base;
        if (kk < 3)      base = w3 + (size_t)(n * 3 + kk) * 2048;
        else if (kk < 7) base = w4 + (size_t)(n * 4 + (kk - 3)) * 2048;
        else             base = w5 + (size_t)(n * 5 + (kk - 7)) * 2048;
        rp = (const float4*)base;
    }

    // Issue first batch of 8 independent LDG.128 BEFORE staging smem.
    float4 buf0[8], buf1[8];
    #pragma unroll
    for (int j = 0; j < 8; j++) buf0[j] = rp[lane + 32 * j];

    const float4* We4 = (const float4*)We;
    const float4* be4 = (const float4*)be;
    for (int i = tid; i < 512; i += 256) {
        sW4[i]        = We4[i];
        sW4[512 + i]  = We4[512 + i];
        sW4[1024 + i] = We4[1024 + i];
        sW4[1536 + i] = We4[1536 + i];
        sW4[2048 + i] = be4[i];
    }

    // Issue second batch — overlaps with smem staging + first-batch FMAs.
    #pragma unroll
    for (int j = 0; j < 8; j++) buf1[j] = rp[256 + lane + 32 * j];

    __syncthreads();

    float acc[5] = {0.f, 0.f, 0.f, 0.f, 0.f};

    #pragma unroll
    for (int j = 0; j < 8; j++) {
        const int l = lane + 32 * j;
        #pragma unroll
        for (int d = 0; d < 5; d++) {
            float4 s = sW4[d * 512 + l];
            acc[d] += buf0[j].x * s.x + buf0[j].y * s.y + buf0[j].z * s.z + buf0[j].w * s.w;
        }
    }
    #pragma unroll
    for (int j = 0; j < 8; j++) {
        const int l = 256 + lane + 32 * j;
        #pragma unroll
        for (int d = 0; d < 5; d++) {
            float4 s = sW4[d * 512 + l];
            acc[d] += buf1[j].x * s.x + buf1[j].y * s.y + buf1[j].z * s.z + buf1[j].w * s.w;
        }
    }

    #pragma unroll
    for (int d = 0; d < 5; d++)
        #pragma unroll
        for (int off = 16; off > 0; off >>= 1)
            acc[d] += __shfl_down_sync(0xffffffffu, acc[d], off);

    if (lane == 0) {
        #pragma unroll
        for (int d = 0; d < 5; d++) g_WeF[d * NKK + rid] = acc[d];
    }
}

// ---------------------------------------------------------------------------
// K2: V[c][j][cls] += sum over valid (kk, p=c-k), n-chunk of
//        relu(LUT[c,j,:].WeF[:,nkk] + WeF[4,nkk]) * W2[feat(K,n,p), cls]
//     128 blocks = 8 c x 16 n-chunks(16 each); 128 threads (thread = cls).
// ---------------------------------------------------------------------------
__global__ void k2_v(const float* __restrict__ LUT, const float* __restrict__ W2)
{
    __shared__ float sr[192 * 16];   // [n_local*12 + kk][j]
    __shared__ float sLUT[64];       // LUT[c][j][d]
    const int tid = threadIdx.x;     // 128
    const int c  = blockIdx.x >> 4;
    const int n0 = (blockIdx.x & 15) * 16;

    if (tid < 64) sLUT[tid] = LUT[c * 64 + tid];
    __syncthreads();

    for (int pr = tid; pr < 192; pr += 128) {
        int nl = pr / 12, kk = pr % 12;
        int nkk = (n0 + nl) * 12 + kk;
        float v0 = g_WeF[nkk];
        float v1 = g_WeF[NKK + nkk];
        float v2 = g_WeF[2 * NKK + nkk];
        float v3 = g_WeF[3 * NKK + nkk];
        float v4 = g_WeF[4 * NKK + nkk];
        #pragma unroll
        for (int j = 0; j < 16; j++) {
            float r = sLUT[j * 4] * v0 + sLUT[j * 4 + 1] * v1 +
                      sLUT[j * 4 + 2] * v2 + sLUT[j * 4 + 3] * v3 + v4;
            sr[pr * 16 + j] = fmaxf(r, 0.f);
        }
    }
    __syncthreads();

    if (tid < NCLS) {
        const int cls = tid;
        float vac[16];
        #pragma unroll
        for (int j = 0; j < 16; j++) vac[j] = 0.f;

        #pragma unroll
        for (int K = 3; K <= 5; K++) {
            const int off = (K == 3) ? 0 : ((K == 4) ? 1536 : 2816);
            const int P   = 9 - K;
            const int kk0 = (K == 3) ? 0 : ((K == 4) ? 3 : 7);
            #pragma unroll
            for (int k = 0; k < 5; k++) {
                if (k >= K) break;
                int p = c - k;
                if (p < 0 || p > P - 1) continue;
                int kk = kk0 + k;
                #pragma unroll 4
                for (int nl = 0; nl < 16; nl++) {
                    int feat = off + (n0 + nl) * P + p;
                    float w2 = W2[feat * NCLS + cls];
                    const float4* r4 = (const float4*)&sr[(nl * 12 + kk) * 16];
                    float4 a = r4[0], b = r4[1], cc = r4[2], d = r4[3];
                    vac[0]  += a.x * w2;  vac[1]  += a.y * w2;
                    vac[2]  += a.z * w2;  vac[3]  += a.w * w2;
                    vac[4]  += b.x * w2;  vac[5]  += b.y * w2;
                    vac[6]  += b.z * w2;  vac[7]  += b.w * w2;
                    vac[8]  += cc.x * w2; vac[9]  += cc.y * w2;
                    vac[10] += cc.z * w2; vac[11] += cc.w * w2;
                    vac[12] += d.x * w2;  vac[13] += d.y * w2;
                    vac[14] += d.z * w2;  vac[15] += d.w * w2;
                }
            }
        }
        #pragma unroll
        for (int j = 0; j < 16; j++)
            atomicAdd(&g_V[(c * 16 + j) * NCLS + cls], vac[j]);
    }
}

// ---------------------------------------------------------------------------
// K3: per-batch-row. One warp per b (512 blocks x 8 warps).
// ---------------------------------------------------------------------------
__global__ void k3_main(const void* __restrict__ xraw,
                        const float* __restrict__ len_emb,
                        const float* __restrict__ ipd_emb,
                        const float* __restrict__ W1, const float* __restrict__ b1,
                        const float* __restrict__ S,  const float* __restrict__ T,
                        const float* __restrict__ H,  const float* __restrict__ b2,
                        float* __restrict__ out)
{
    __shared__ float sW1[128], sb1[4], sS[480], sT[120], sH[240], sb2[NCLS];
    const int tid = threadIdx.x;
    if (tid < 128) sW1[tid] = W1[tid];
    if (tid < 4)   sb1[tid] = b1[tid];
    for (int i = tid; i < 480; i += 256) sS[i] = S[i];
    if (tid < 120) sT[tid] = T[tid];
    if (tid < 240) sH[tid] = H[tid];
    if (tid < NCLS) sb2[tid] = b2[tid];
    __syncthreads();

    const int warp = tid >> 5, lane = tid & 31;
    const int b = blockIdx.x * 8 + warp;
    const int is64 = g_x64;

    int idx = 0;
    if (lane < 8) {
        const int c = lane;
        int i0, i1;
        if (is64) {
            const long long* xp = (const long long*)xraw;
            i0 = (int)xp[((size_t)b * 8 + c) * 2];
            i1 = (int)xp[((size_t)b * 8 + c) * 2 + 1];
        } else {
            const int* xp = (const int*)xraw;
            i0 = xp[((size_t)b * 8 + c) * 2];
            i1 = xp[((size_t)b * 8 + c) * 2 + 1];
        }

        float h4[4] = {0.f, 0.f, 0.f, 0.f};
        const float4* le4 = (const float4*)(len_emb + (size_t)i0 * 16);
        #pragma unroll
        for (int q = 0; q < 4; q++) {
            float4 v = le4[q];
            const float vv[4] = {v.x, v.y, v.z, v.w};
            #pragma unroll
            for (int s = 0; s < 4; s++) {
                int i = q * 4 + s;
                #pragma unroll
                for (int d = 0; d < 4; d++) h4[d] += vv[s] * sW1[i * 4 + d];
            }
        }
        const float4* ie4 = (const float4*)(ipd_emb + (size_t)i1 * 16);
        #pragma unroll
        for (int q = 0; q < 4; q++) {
            float4 v = ie4[q];
            const float vv[4] = {v.x, v.y, v.z, v.w};
            #pragma unroll
            for (int s = 0; s < 4; s++) {
                int i = 16 + q * 4 + s;
                #pragma unroll
                for (int d = 0; d < 4; d++) h4[d] += vv[s] * sW1[i * 4 + d];
            }
        }
        #pragma unroll
        for (int d = 0; d < 4; d++) h4[d] += sb1[d];

        float m16[16];
        #pragma unroll
        for (int j = 0; j < 16; j++) m16[j] = 0.f;

        #pragma unroll
        for (int k = 0; k < 15; k++) {
            float acc = 0.f;
            #pragma unroll
            for (int d = 0; d < 4; d++) acc += h4[d] * sS[(c * 4 + d) * 15 + k];
            float m = (acc - sT[c * 15 + k]) - 1e-4f;
            float sgn = (m > 0.f) ? 1.f : ((m < 0.f) ? -1.f : 0.f);
            #pragma unroll
            for (int j = 0; j < 16; j++) m16[j] += sgn * sH[k * 16 + j];
        }

        float bm = m16[0];
        #pragma unroll
        for (int j = 1; j < 16; j++)
            if (m16[j] > bm) { bm = m16[j]; idx = j; }   // first-max (strict >)
    }

    int vrow[8];
    #pragma unroll
    for (int h = 0; h < 8; h++) {
        int ih = __shfl_sync(0xffffffffu, idx, h);
        vrow[h] = (h * 16 + ih) * NCLS;
    }

    float lg[4];
    #pragma unroll
    for (int t = 0; t < 4; t++) {
        int cls = lane + 32 * t;
        if (cls < NCLS) {
            float v = sb2[cls];
            #pragma unroll
            for (int h = 0; h < 8; h++) v += g_V[vrow[h] + cls];
            lg[t] = v;
        } else {
            lg[t] = -INFINITY;
        }
    }

    float M = fmaxf(fmaxf(lg[0], lg[1]), fmaxf(lg[2], lg[3]));
    #pragma unroll
    for (int off = 16; off > 0; off >>= 1)
        M = fmaxf(M, __shfl_xor_sync(0xffffffffu, M, off));

    float ss = 0.f;
    #pragma unroll
    for (int t = 0; t < 4; t++) ss += expf(lg[t] - M);
    #pragma unroll
    for (int off = 16; off > 0; off >>= 1)
        ss += __shfl_xor_sync(0xffffffffu, ss, off);

    float lse = M + logf(ss);
    #pragma unroll
    for (int t = 0; t < 4; t++) {
        int cls = lane + 32 * t;
        if (cls < NCLS) out[(size_t)b * NCLS + cls] = lg[t] - lse;
    }
}

// ---------------------------------------------------------------------------
extern "C" void kernel_launch(void* const* d_in, const int* in_sizes, int n_in,
                              void* d_out, int out_size)
{
    (void)in_sizes; (void)n_in; (void)out_size;
    const void*  x       = d_in[0];
    const float* len_emb = (const float*)d_in[1];
    const float* ipd_emb = (const float*)d_in[2];
    const float* W1      = (const float*)d_in[3];
    const float* b1      = (const float*)d_in[4];
    const float* We      = (const float*)d_in[5];
    const float* be      = (const float*)d_in[6];
    const float* w3      = (const float*)d_in[7];
    const float* w4      = (const float*)d_in[8];
    const float* w5      = (const float*)d_in[9];
    const float* W2      = (const float*)d_in[10];
    const float* b2      = (const float*)d_in[11];
    const float* S       = (const float*)d_in[12];
    const float* H       = (const float*)d_in[13];
    const float* T       = (const float*)d_in[14];
    const float* LUT     = (const float*)d_in[15];
    float* out = (float*)d_out;

    k1_wef<<<384, 256>>>(We, be, w3, w4, w5, x);
    k2_v<<<128, 128>>>(LUT, W2);
    k3_main<<<512, 256>>>(x, len_emb, ipd_emb, W1, b1, S, T, H, b2, out);
}

// round 5
// speedup vs baseline: 1.1160x; 1.1160x over previous
#include <cuda_runtime.h>
#include <math.h>

// ---------------------------------------------------------------------------
// Problem constants
//  B=4096, SEQ=C=8, D=4, L=2048, NK=256, NCLS=100
//  filters: w3 (256,3,2048), w4 (256,4,2048), w5 (256,5,2048) -> 3072 rows
// ---------------------------------------------------------------------------

#define NKK 3072           // total filter rows (n*12 + kk), kk: 0-2 K3, 3-6 K4, 7-11 K5
#define NCLS 100

__device__ float g_WeFp[2 * 5 * NKK]; // [chunk][d][nkk]; d=4 holds be-projection
__device__ float g_V[8 * 16 * NCLS];  // per (position h, code j) logit contribution
__device__ int   g_x64;               // 1 if x is int64, 0 if int32

// ---------------------------------------------------------------------------
// K1: WeFp[ch][d][nkk] = sum_{l in chunk ch} {We[d,:],be}[l] * w_row[nkk][l]
//     Split-L: 768 blocks (384 row-groups x 2 L-chunks of 1024), 256 thr.
//     Warp owns one (row, chunk): exactly 8 front-batched LDG.128 per lane.
//     Low regs -> ~32 warps/SM resident -> deep MLP chip-wide.
// ---------------------------------------------------------------------------
__global__ void __launch_bounds__(256)
k1_wef(const float* __restrict__ We, const float* __restrict__ be,
       const float* __restrict__ w3, const float* __restrict__ w4,
       const float* __restrict__ w5, const void* __restrict__ xraw)
{
    __shared__ float4 sW4[5 * 256];   // [d][l4 within chunk]  (20 KB)
    const int tid = threadIdx.x;

    if (blockIdx.x == 0 && tid == 0) {
        // int64 layout -> odd int32 words all zero (values in [0,1500))
        const int* xi = (const int*)xraw;
        int any = 0;
        #pragma unroll 1
        for (int i = 1; i < 256; i += 2) any |= xi[i];
        g_x64 = (any == 0) ? 1 : 0;
    }

    {
        int gz = blockIdx.x * 256 + tid;
        if (gz < 8 * 16 * NCLS) g_V[gz] = 0.f;
    }

    const int warp = tid >> 5, lane = tid & 31;
    const int rowgrp = blockIdx.x >> 1;
    const int ch     = blockIdx.x & 1;       // L-chunk: 0 -> [0,1024), 1 -> [1024,2048)
    const int rid    = rowgrp * 8 + warp;

    const float4* rp;
    {
        int n = rid / 12, kk = rid % 12;
        const float* base;
        if (kk < 3)      base = w3 + (size_t)(n * 3 + kk) * 2048;
        else if (kk < 7) base = w4 + (size_t)(n * 4 + (kk - 3)) * 2048;
        else             base = w5 + (size_t)(n * 5 + (kk - 7)) * 2048;
        rp = (const float4*)base + ch * 256;
    }

    // Front-batch: 8 independent LDG.128 per lane (whole chunk for this row).
    float4 buf[8];
    #pragma unroll
    for (int j = 0; j < 8; j++) buf[j] = rp[lane + 32 * j];

    // Stage We chunk while the loads are in flight.
    const float4* We4 = (const float4*)We;
    const float4* be4 = (const float4*)be;
    {
        const int i = tid;   // 256 threads cover 256 float4 per d
        sW4[i]            = We4[ch * 256 + i];
        sW4[256 + i]      = We4[512 + ch * 256 + i];
        sW4[512 + i]      = We4[1024 + ch * 256 + i];
        sW4[768 + i]      = We4[1536 + ch * 256 + i];
        sW4[1024 + i]     = be4[ch * 256 + i];
    }
    __syncthreads();

    float acc[5] = {0.f, 0.f, 0.f, 0.f, 0.f};
    #pragma unroll
    for (int j = 0; j < 8; j++) {
        const int l = lane + 32 * j;
        #pragma unroll
        for (int d = 0; d < 5; d++) {
            float4 s = sW4[d * 256 + l];
            acc[d] += buf[j].x * s.x + buf[j].y * s.y + buf[j].z * s.z + buf[j].w * s.w;
        }
    }

    #pragma unroll
    for (int d = 0; d < 5; d++)
        #pragma unroll
        for (int off = 16; off > 0; off >>= 1)
            acc[d] += __shfl_down_sync(0xffffffffu, acc[d], off);

    if (lane == 0) {
        #pragma unroll
        for (int d = 0; d < 5; d++)
            g_WeFp[ch * 5 * NKK + d * NKK + rid] = acc[d];
    }
}

// ---------------------------------------------------------------------------
// K2: V[c][j][cls] += sum over valid (kk, p=c-k), n-chunk of
//        relu(LUT[c,j,:].WeF[:,nkk] + WeF[4,nkk]) * W2[feat(K,n,p), cls]
//     256 blocks = 8 c x 32 n-chunks(8 each); 128 threads (thread = cls).
// ---------------------------------------------------------------------------
__global__ void k2_v(const float* __restrict__ LUT, const float* __restrict__ W2)
{
    __shared__ float sr[96 * 16];    // [n_local*12 + kk][j]
    __shared__ float sLUT[64];       // LUT[c][j][d]
    const int tid = threadIdx.x;     // 128
    const int c  = blockIdx.x >> 5;
    const int n0 = (blockIdx.x & 31) * 8;

    if (tid < 64) sLUT[tid] = LUT[c * 64 + tid];
    __syncthreads();

    if (tid < 96) {
        int nl = tid / 12, kk = tid % 12;
        int nkk = (n0 + nl) * 12 + kk;
        float v0 = g_WeFp[nkk]           + g_WeFp[5 * NKK + nkk];
        float v1 = g_WeFp[NKK + nkk]     + g_WeFp[6 * NKK + nkk];
        float v2 = g_WeFp[2 * NKK + nkk] + g_WeFp[7 * NKK + nkk];
        float v3 = g_WeFp[3 * NKK + nkk] + g_WeFp[8 * NKK + nkk];
        float v4 = g_WeFp[4 * NKK + nkk] + g_WeFp[9 * NKK + nkk];
        #pragma unroll
        for (int j = 0; j < 16; j++) {
            float r = sLUT[j * 4] * v0 + sLUT[j * 4 + 1] * v1 +
                      sLUT[j * 4 + 2] * v2 + sLUT[j * 4 + 3] * v3 + v4;
            sr[tid * 16 + j] = fmaxf(r, 0.f);
        }
    }
    __syncthreads();

    if (tid < NCLS) {
        const int cls = tid;
        float vac[16];
        #pragma unroll
        for (int j = 0; j < 16; j++) vac[j] = 0.f;

        #pragma unroll
        for (int K = 3; K <= 5; K++) {
            const int off = (K == 3) ? 0 : ((K == 4) ? 1536 : 2816);
            const int P   = 9 - K;
            const int kk0 = (K == 3) ? 0 : ((K == 4) ? 3 : 7);
            #pragma unroll
            for (int k = 0; k < 5; k++) {
                if (k >= K) break;
                int p = c - k;
                if (p < 0 || p > P - 1) continue;
                int kk = kk0 + k;
                #pragma unroll
                for (int nl = 0; nl < 8; nl++) {
                    int feat = off + (n0 + nl) * P + p;
                    float w2 = W2[feat * NCLS + cls];
                    const float4* r4 = (const float4*)&sr[(nl * 12 + kk) * 16];
                    float4 a = r4[0], b = r4[1], cc = r4[2], d = r4[3];
                    vac[0]  += a.x * w2;  vac[1]  += a.y * w2;
                    vac[2]  += a.z * w2;  vac[3]  += a.w * w2;
                    vac[4]  += b.x * w2;  vac[5]  += b.y * w2;
                    vac[6]  += b.z * w2;  vac[7]  += b.w * w2;
                    vac[8]  += cc.x * w2; vac[9]  += cc.y * w2;
                    vac[10] += cc.z * w2; vac[11] += cc.w * w2;
                    vac[12] += d.x * w2;  vac[13] += d.y * w2;
                    vac[14] += d.z * w2;  vac[15] += d.w * w2;
                }
            }
        }
        #pragma unroll
        for (int j = 0; j < 16; j++)
            atomicAdd(&g_V[(c * 16 + j) * NCLS + cls], vac[j]);
    }
}

// ---------------------------------------------------------------------------
// K3: per-batch-row. One warp per b (512 blocks x 8 warps).
// ---------------------------------------------------------------------------
__global__ void k3_main(const void* __restrict__ xraw,
                        const float* __restrict__ len_emb,
                        const float* __restrict__ ipd_emb,
                        const float* __restrict__ W1, const float* __restrict__ b1,
                        const float* __restrict__ S,  const float* __restrict__ T,
                        const float* __restrict__ H,  const float* __restrict__ b2,
                        float* __restrict__ out)
{
    __shared__ float sW1[128], sb1[4], sS[480], sT[120], sH[240], sb2[NCLS];
    const int tid = threadIdx.x;
    if (tid < 128) sW1[tid] = W1[tid];
    if (tid < 4)   sb1[tid] = b1[tid];
    for (int i = tid; i < 480; i += 256) sS[i] = S[i];
    if (tid < 120) sT[tid] = T[tid];
    if (tid < 240) sH[tid] = H[tid];
    if (tid < NCLS) sb2[tid] = b2[tid];
    __syncthreads();

    const int warp = tid >> 5, lane = tid & 31;
    const int b = blockIdx.x * 8 + warp;
    const int is64 = g_x64;

    int idx = 0;
    if (lane < 8) {
        const int c = lane;
        int i0, i1;
        if (is64) {
            const long long* xp = (const long long*)xraw;
            i0 = (int)xp[((size_t)b * 8 + c) * 2];
            i1 = (int)xp[((size_t)b * 8 + c) * 2 + 1];
        } else {
            const int* xp = (const int*)xraw;
            i0 = xp[((size_t)b * 8 + c) * 2];
            i1 = xp[((size_t)b * 8 + c) * 2 + 1];
        }

        float h4[4] = {0.f, 0.f, 0.f, 0.f};
        const float4* le4 = (const float4*)(len_emb + (size_t)i0 * 16);
        #pragma unroll
        for (int q = 0; q < 4; q++) {
            float4 v = le4[q];
            const float vv[4] = {v.x, v.y, v.z, v.w};
            #pragma unroll
            for (int s = 0; s < 4; s++) {
                int i = q * 4 + s;
                #pragma unroll
                for (int d = 0; d < 4; d++) h4[d] += vv[s] * sW1[i * 4 + d];
            }
        }
        const float4* ie4 = (const float4*)(ipd_emb + (size_t)i1 * 16);
        #pragma unroll
        for (int q = 0; q < 4; q++) {
            float4 v = ie4[q];
            const float vv[4] = {v.x, v.y, v.z, v.w};
            #pragma unroll
            for (int s = 0; s < 4; s++) {
                int i = 16 + q * 4 + s;
                #pragma unroll
                for (int d = 0; d < 4; d++) h4[d] += vv[s] * sW1[i * 4 + d];
            }
        }
        #pragma unroll
        for (int d = 0; d < 4; d++) h4[d] += sb1[d];

        float m16[16];
        #pragma unroll
        for (int j = 0; j < 16; j++) m16[j] = 0.f;

        #pragma unroll
        for (int k = 0; k < 15; k++) {
            float acc = 0.f;
            #pragma unroll
            for (int d = 0; d < 4; d++) acc += h4[d] * sS[(c * 4 + d) * 15 + k];
            float m = (acc - sT[c * 15 + k]) - 1e-4f;
            float sgn = (m > 0.f) ? 1.f : ((m < 0.f) ? -1.f : 0.f);
            #pragma unroll
            for (int j = 0; j < 16; j++) m16[j] += sgn * sH[k * 16 + j];
        }

        float bm = m16[0];
        #pragma unroll
        for (int j = 1; j < 16; j++)
            if (m16[j] > bm) { bm = m16[j]; idx = j; }   // first-max (strict >)
    }

    int vrow[8];
    #pragma unroll
    for (int h = 0; h < 8; h++) {
        int ih = __shfl_sync(0xffffffffu, idx, h);
        vrow[h] = (h * 16 + ih) * NCLS;
    }

    float lg[4];
    #pragma unroll
    for (int t = 0; t < 4; t++) {
        int cls = lane + 32 * t;
        if (cls < NCLS) {
            float v = sb2[cls];
            #pragma unroll
            for (int h = 0; h < 8; h++) v += g_V[vrow[h] + cls];
            lg[t] = v;
        } else {
            lg[t] = -INFINITY;
        }
    }

    float M = fmaxf(fmaxf(lg[0], lg[1]), fmaxf(lg[2], lg[3]));
    #pragma unroll
    for (int off = 16; off > 0; off >>= 1)
        M = fmaxf(M, __shfl_xor_sync(0xffffffffu, M, off));

    float ss = 0.f;
    #pragma unroll
    for (int t = 0; t < 4; t++) ss += expf(lg[t] - M);
    #pragma unroll
    for (int off = 16; off > 0; off >>= 1)
        ss += __shfl_xor_sync(0xffffffffu, ss, off);

    float lse = M + logf(ss);
    #pragma unroll
    for (int t = 0; t < 4; t++) {
        int cls = lane + 32 * t;
        if (cls < NCLS) out[(size_t)b * NCLS + cls] = lg[t] - lse;
    }
}

// ---------------------------------------------------------------------------
extern "C" void kernel_launch(void* const* d_in, const int* in_sizes, int n_in,
                              void* d_out, int out_size)
{
    (void)in_sizes; (void)n_in; (void)out_size;
    const void*  x       = d_in[0];
    const float* len_emb = (const float*)d_in[1];
    const float* ipd_emb = (const float*)d_in[2];
    const float* W1      = (const float*)d_in[3];
    const float* b1      = (const float*)d_in[4];
    const float* We      = (const float*)d_in[5];
    const float* be      = (const float*)d_in[6];
    const float* w3      = (const float*)d_in[7];
    const float* w4      = (const float*)d_in[8];
    const float* w5      = (const float*)d_in[9];
    const float* W2      = (const float*)d_in[10];
    const float* b2      = (const float*)d_in[11];
    const float* S       = (const float*)d_in[12];
    const float* H       = (const float*)d_in[13];
    const float* T       = (const float*)d_in[14];
    const float* LUT     = (const float*)d_in[15];
    float* out = (float*)d_out;

    k1_wef<<<768, 256>>>(We, be, w3, w4, w5, x);
    k2_v<<<256, 128>>>(LUT, W2);
    k3_main<<<512, 256>>>(x, len_emb, ipd_emb, W1, b1, S, T, H, b2, out);
}

// round 6
// speedup vs baseline: 1.1769x; 1.0545x over previous
#include <cuda_runtime.h>
#include <math.h>

// ---------------------------------------------------------------------------
// Problem constants
//  B=4096, SEQ=C=8, D=4, L=2048, NK=256, NCLS=100
//  filters: w3 (256,3,2048), w4 (256,4,2048), w5 (256,5,2048) -> 3072 rows
// ---------------------------------------------------------------------------

#define NKK 3072
#define NCLS 100

__device__ float g_WeFp[2 * 5 * NKK]; // [chunk][d][nkk]; d=4 holds be-projection
__device__ float g_V[8 * 16 * NCLS];
__device__ int   g_x64;

// ---------------------------------------------------------------------------
// K1: WeFp[ch][d][nkk] = sum_{l in half ch} {We[d,:],be}[l] * w_row[nkk][l]
//     384 blocks (192 row-groups x 2 L-halves), 256 thr. Warp owns 2 rows;
//     4 pipelined iterations of 256 floats with double-buffered prefetch,
//     so DRAM requests stream instead of burst-then-stall.
// ---------------------------------------------------------------------------
__global__ void __launch_bounds__(256)
k1_wef(const float* __restrict__ We, const float* __restrict__ be,
       const float* __restrict__ w3, const float* __restrict__ w4,
       const float* __restrict__ w5, const void* __restrict__ xraw)
{
    __shared__ float4 sW4[5 * 256];   // [d][l4 within half]  (20 KB)
    const int tid = threadIdx.x;

    if (blockIdx.x == 0 && tid == 0) {
        const int* xi = (const int*)xraw;
        int any = 0;
        #pragma unroll 1
        for (int i = 1; i < 256; i += 2) any |= xi[i];
        g_x64 = (any == 0) ? 1 : 0;
    }
    {
        int gz = blockIdx.x * 256 + tid;
        if (gz < 8 * 16 * NCLS) g_V[gz] = 0.f;
    }

    const int warp = tid >> 5, lane = tid & 31;
    const int grp  = blockIdx.x >> 1;     // 192 groups of 16 rows
    const int ch   = blockIdx.x & 1;      // L-half
    const int rid0 = grp * 16 + warp * 2;

    const float4 *rp0, *rp1;
    {
        #pragma unroll
        for (int r = 0; r < 2; r++) {
            int rid = rid0 + r;
            int n = rid / 12, kk = rid % 12;
            const float* base;
            if (kk < 3)      base = w3 + (size_t)(n * 3 + kk) * 2048;
            else if (kk < 7) base = w4 + (size_t)(n * 4 + (kk - 3)) * 2048;
            else             base = w5 + (size_t)(n * 5 + (kk - 7)) * 2048;
            if (r == 0) rp0 = (const float4*)base + ch * 256;
            else        rp1 = (const float4*)base + ch * 256;
        }
    }

    // Prefetch iteration 0 (4 independent LDG.128).
    float4 bufA[4], bufB[4];
    bufA[0] = rp0[lane];      bufA[1] = rp0[32 + lane];
    bufA[2] = rp1[lane];      bufA[3] = rp1[32 + lane];

    // Stage We half while loads are in flight.
    const float4* We4 = (const float4*)We;
    const float4* be4 = (const float4*)be;
    sW4[tid]            = We4[ch * 256 + tid];
    sW4[256 + tid]      = We4[512 + ch * 256 + tid];
    sW4[512 + tid]      = We4[1024 + ch * 256 + tid];
    sW4[768 + tid]      = We4[1536 + ch * 256 + tid];
    sW4[1024 + tid]     = be4[ch * 256 + tid];
    __syncthreads();

    float acc[2][5];
    #pragma unroll
    for (int r = 0; r < 2; r++)
        #pragma unroll
        for (int d = 0; d < 5; d++) acc[r][d] = 0.f;

    #pragma unroll
    for (int it = 0; it < 4; it++) {
        float4* cur = (it & 1) ? bufB : bufA;
        float4* nxt = (it & 1) ? bufA : bufB;
        if (it < 3) {
            const int o = (it + 1) * 64;
            nxt[0] = rp0[o + lane];      nxt[1] = rp0[o + 32 + lane];
            nxt[2] = rp1[o + lane];      nxt[3] = rp1[o + 32 + lane];
        }
        const int l0 = it * 64 + lane, l1 = it * 64 + 32 + lane;
        #pragma unroll
        for (int d = 0; d < 5; d++) {
            float4 s0 = sW4[d * 256 + l0];
            float4 s1 = sW4[d * 256 + l1];
            acc[0][d] += cur[0].x * s0.x + cur[0].y * s0.y + cur[0].z * s0.z + cur[0].w * s0.w
                       + cur[1].x * s1.x + cur[1].y * s1.y + cur[1].z * s1.z + cur[1].w * s1.w;
            acc[1][d] += cur[2].x * s0.x + cur[2].y * s0.y + cur[2].z * s0.z + cur[2].w * s0.w
                       + cur[3].x * s1.x + cur[3].y * s1.y + cur[3].z * s1.z + cur[3].w * s1.w;
        }
    }

    #pragma unroll
    for (int r = 0; r < 2; r++)
        #pragma unroll
        for (int d = 0; d < 5; d++)
            #pragma unroll
            for (int off = 16; off > 0; off >>= 1)
                acc[r][d] += __shfl_down_sync(0xffffffffu, acc[r][d], off);

    if (lane == 0) {
        #pragma unroll
        for (int r = 0; r < 2; r++)
            #pragma unroll
            for (int d = 0; d < 5; d++)
                g_WeFp[ch * 5 * NKK + d * NKK + (rid0 + r)] = acc[r][d];
    }
}

// ---------------------------------------------------------------------------
// K2: 256 blocks = 8 c x 32 n-chunks(8 each); 128 threads (thread = cls).
// ---------------------------------------------------------------------------
__global__ void k2_v(const float* __restrict__ LUT, const float* __restrict__ W2)
{
    __shared__ float sr[96 * 16];
    __shared__ float sLUT[64];
    const int tid = threadIdx.x;     // 128
    const int c  = blockIdx.x >> 5;
    const int n0 = (blockIdx.x & 31) * 8;

    if (tid < 64) sLUT[tid] = LUT[c * 64 + tid];
    __syncthreads();

    if (tid < 96) {
        int nl = tid / 12, kk = tid % 12;
        int nkk = (n0 + nl) * 12 + kk;
        float v0 = g_WeFp[nkk]           + g_WeFp[5 * NKK + nkk];
        float v1 = g_WeFp[NKK + nkk]     + g_WeFp[6 * NKK + nkk];
        float v2 = g_WeFp[2 * NKK + nkk] + g_WeFp[7 * NKK + nkk];
        float v3 = g_WeFp[3 * NKK + nkk] + g_WeFp[8 * NKK + nkk];
        float v4 = g_WeFp[4 * NKK + nkk] + g_WeFp[9 * NKK + nkk];
        #pragma unroll
        for (int j = 0; j < 16; j++) {
            float r = sLUT[j * 4] * v0 + sLUT[j * 4 + 1] * v1 +
                      sLUT[j * 4 + 2] * v2 + sLUT[j * 4 + 3] * v3 + v4;
            sr[tid * 16 + j] = fmaxf(r, 0.f);
        }
    }
    __syncthreads();

    if (tid < NCLS) {
        const int cls = tid;
        float vac[16];
        #pragma unroll
        for (int j = 0; j < 16; j++) vac[j] = 0.f;

        #pragma unroll
        for (int K = 3; K <= 5; K++) {
            const int off = (K == 3) ? 0 : ((K == 4) ? 1536 : 2816);
            const int P   = 9 - K;
            const int kk0 = (K == 3) ? 0 : ((K == 4) ? 3 : 7);
            #pragma unroll
            for (int k = 0; k < 5; k++) {
                if (k >= K) break;
                int p = c - k;
                if (p < 0 || p > P - 1) continue;
                int kk = kk0 + k;
                #pragma unroll
                for (int nl = 0; nl < 8; nl++) {
                    int feat = off + (n0 + nl) * P + p;
                    float w2 = W2[feat * NCLS + cls];
                    const float4* r4 = (const float4*)&sr[(nl * 12 + kk) * 16];
                    float4 a = r4[0], b = r4[1], cc = r4[2], d = r4[3];
                    vac[0]  += a.x * w2;  vac[1]  += a.y * w2;
                    vac[2]  += a.z * w2;  vac[3]  += a.w * w2;
                    vac[4]  += b.x * w2;  vac[5]  += b.y * w2;
                    vac[6]  += b.z * w2;  vac[7]  += b.w * w2;
                    vac[8]  += cc.x * w2; vac[9]  += cc.y * w2;
                    vac[10] += cc.z * w2; vac[11] += cc.w * w2;
                    vac[12] += d.x * w2;  vac[13] += d.y * w2;
                    vac[14] += d.z * w2;  vac[15] += d.w * w2;
                }
            }
        }
        #pragma unroll
        for (int j = 0; j < 16; j++)
            atomicAdd(&g_V[(c * 16 + j) * NCLS + cls], vac[j]);
    }
}

// ---------------------------------------------------------------------------
// K3: one warp per b. Lane = 4*c + q: all 32 lanes share the embedding and
//     sign-net work (4-lane groups per position c), reduced via shfl_xor
//     (commutative-only reordering -> deterministic).
// ---------------------------------------------------------------------------
__global__ void k3_main(const void* __restrict__ xraw,
                        const float* __restrict__ len_emb,
                        const float* __restrict__ ipd_emb,
                        const float* __restrict__ W1, const float* __restrict__ b1,
                        const float* __restrict__ S,  const float* __restrict__ T,
                        const float* __restrict__ H,  const float* __restrict__ b2,
                        float* __restrict__ out)
{
    __shared__ float sW1[128], sb1[4], sS[480], sT[120], sH[240], sb2[NCLS];
    const int tid = threadIdx.x;
    if (tid < 128) sW1[tid] = W1[tid];
    if (tid < 4)   sb1[tid] = b1[tid];
    for (int i = tid; i < 480; i += 256) sS[i] = S[i];
    if (tid < 120) sT[tid] = T[tid];
    if (tid < 240) sH[tid] = H[tid];
    if (tid < NCLS) sb2[tid] = b2[tid];
    __syncthreads();

    const int warp = tid >> 5, lane = tid & 31;
    const int b = blockIdx.x * 8 + warp;
    const int is64 = g_x64;

    const int c = lane >> 2;     // position 0..7
    const int q = lane & 3;      // quarter of the 16-dim embedding

    // indices (all 4 lanes of a group load the same -> L1 broadcast)
    int i0, i1;
    if (is64) {
        const long long* xp = (const long long*)xraw;
        i0 = (int)xp[((size_t)b * 8 + c) * 2];
        i1 = (int)xp[((size_t)b * 8 + c) * 2 + 1];
    } else {
        const int* xp = (const int*)xraw;
        i0 = xp[((size_t)b * 8 + c) * 2];
        i1 = xp[((size_t)b * 8 + c) * 2 + 1];
    }

    // partial h4: this lane covers embedding dims [q*4, q*4+4)
    float4 vl = ((const float4*)(len_emb + (size_t)i0 * 16))[q];
    float4 vi = ((const float4*)(ipd_emb + (size_t)i1 * 16))[q];

    float h4[4] = {0.f, 0.f, 0.f, 0.f};
    {
        const float lv[4] = {vl.x, vl.y, vl.z, vl.w};
        const float iv[4] = {vi.x, vi.y, vi.z, vi.w};
        #pragma unroll
        for (int s = 0; s < 4; s++) {
            const int il = q * 4 + s;
            const int ii = 16 + q * 4 + s;
            #pragma unroll
            for (int d = 0; d < 4; d++) {
                h4[d] += lv[s] * sW1[il * 4 + d];
                h4[d] += iv[s] * sW1[ii * 4 + d];
            }
        }
    }
    // reduce across the 4-lane group
    #pragma unroll
    for (int d = 0; d < 4; d++) {
        h4[d] += __shfl_xor_sync(0xffffffffu, h4[d], 1);
        h4[d] += __shfl_xor_sync(0xffffffffu, h4[d], 2);
        h4[d] += sb1[d];
    }

    // sign-net: lane q handles k = q, q+4, q+8, q+12 (<15)
    float m16[16];
    #pragma unroll
    for (int j = 0; j < 16; j++) m16[j] = 0.f;

    #pragma unroll
    for (int kq = 0; kq < 4; kq++) {
        const int k = q + kq * 4;
        if (k < 15) {
            float a = 0.f;
            #pragma unroll
            for (int d = 0; d < 4; d++) a += h4[d] * sS[(c * 4 + d) * 15 + k];
            float m = (a - sT[c * 15 + k]) - 1e-4f;
            float sgn = (m > 0.f) ? 1.f : ((m < 0.f) ? -1.f : 0.f);
            #pragma unroll
            for (int j = 0; j < 16; j++) m16[j] += sgn * sH[k * 16 + j];
        }
    }
    #pragma unroll
    for (int j = 0; j < 16; j++) {
        m16[j] += __shfl_xor_sync(0xffffffffu, m16[j], 1);
        m16[j] += __shfl_xor_sync(0xffffffffu, m16[j], 2);
    }

    // first-max argmax (identical on all lanes of the group)
    int idx = 0;
    {
        float bm = m16[0];
        #pragma unroll
        for (int j = 1; j < 16; j++)
            if (m16[j] > bm) { bm = m16[j]; idx = j; }
    }

    int vrow[8];
    #pragma unroll
    for (int h = 0; h < 8; h++) {
        int ih = __shfl_sync(0xffffffffu, idx, h * 4);
        vrow[h] = (h * 16 + ih) * NCLS;
    }

    float lg[4];
    #pragma unroll
    for (int t = 0; t < 4; t++) {
        int cls = lane + 32 * t;
        if (cls < NCLS) {
            float v = sb2[cls];
            #pragma unroll
            for (int h = 0; h < 8; h++) v += g_V[vrow[h] + cls];
            lg[t] = v;
        } else {
            lg[t] = -INFINITY;
        }
    }

    float M = fmaxf(fmaxf(lg[0], lg[1]), fmaxf(lg[2], lg[3]));
    #pragma unroll
    for (int off = 16; off > 0; off >>= 1)
        M = fmaxf(M, __shfl_xor_sync(0xffffffffu, M, off));

    float ss = 0.f;
    #pragma unroll
    for (int t = 0; t < 4; t++) ss += expf(lg[t] - M);
    #pragma unroll
    for (int off = 16; off > 0; off >>= 1)
        ss += __shfl_xor_sync(0xffffffffu, ss, off);

    float lse = M + logf(ss);
    #pragma unroll
    for (int t = 0; t < 4; t++) {
        int cls = lane + 32 * t;
        if (cls < NCLS) out[(size_t)b * NCLS + cls] = lg[t] - lse;
    }
}

// ---------------------------------------------------------------------------
extern "C" void kernel_launch(void* const* d_in, const int* in_sizes, int n_in,
                              void* d_out, int out_size)
{
    (void)in_sizes; (void)n_in; (void)out_size;
    const void*  x       = d_in[0];
    const float* len_emb = (const float*)d_in[1];
    const float* ipd_emb = (const float*)d_in[2];
    const float* W1      = (const float*)d_in[3];
    const float* b1      = (const float*)d_in[4];
    const float* We      = (const float*)d_in[5];
    const float* be      = (const float*)d_in[6];
    const float* w3      = (const float*)d_in[7];
    const float* w4      = (const float*)d_in[8];
    const float* w5      = (const float*)d_in[9];
    const float* W2      = (const float*)d_in[10];
    const float* b2      = (const float*)d_in[11];
    const float* S       = (const float*)d_in[12];
    const float* H       = (const float*)d_in[13];
    const float* T       = (const float*)d_in[14];
    const float* LUT     = (const float*)d_in[15];
    float* out = (float*)d_out;

    k1_wef<<<384, 256>>>(We, be, w3, w4, w5, x);
    k2_v<<<256, 128>>>(LUT, W2);
    k3_main<<<512, 256>>>(x, len_emb, ipd_emb, W1, b1, S, T, H, b2, out);
}

// round 7
// speedup vs baseline: 1.3602x; 1.1558x over previous
#include <cuda_runtime.h>
#include <math.h>

// ---------------------------------------------------------------------------
// Problem constants
//  B=4096, SEQ=C=8, D=4, L=2048, NK=256, NCLS=100
//  filters: w3 (256,3,2048), w4 (256,4,2048), w5 (256,5,2048) -> 3072 rows
// ---------------------------------------------------------------------------

#define NKK 3072
#define NCLS 100

__device__ float g_WeFp[2 * 5 * NKK]; // [chunk][d][nkk]; d=4 holds be-projection
__device__ float g_V[8 * 16 * NCLS];
__device__ int   g_x64;

// ---------------------------------------------------------------------------
// K1: WeFp[ch][d][nkk] = sum_{l in half ch} {We[d,:],be}[l] * w_row[nkk][l]
//     One exact wave: 256 blocks x 8 warps = 2048 warps; 6144 (row,half)
//     units = 3 per warp. 6-batch software pipeline (4 LDG.128 per batch,
//     depth-1 prefetch across unit boundaries) -> continuous streaming.
// ---------------------------------------------------------------------------
__global__ void __launch_bounds__(256)
k1_wef(const float* __restrict__ We, const float* __restrict__ be,
       const float* __restrict__ w3, const float* __restrict__ w4,
       const float* __restrict__ w5, const void* __restrict__ xraw)
{
    __shared__ float4 sW4[5 * 512];   // [d][l4 in 0..511]  (40 KB)
    const int tid = threadIdx.x;

    // Parallel dtype detect: warp 0 of block 0, one round trip.
    if (blockIdx.x == 0 && tid < 32) {
        const int* xi = (const int*)xraw;
        int any = 0;
        #pragma unroll
        for (int j = 0; j < 4; j++) any |= xi[1 + 2 * (tid + 32 * j)];
        int anyw = __any_sync(0xffffffffu, any != 0);
        if (tid == 0) g_x64 = anyw ? 0 : 1;
    }
    {
        int gz = blockIdx.x * 256 + tid;
        if (gz < 8 * 16 * NCLS) g_V[gz] = 0.f;
    }

    const int lane = tid & 31;
    const int gw   = blockIdx.x * 8 + (tid >> 5);   // global warp 0..2047

    // Unit pointers (3 units per warp): u = gw*3 + t; rid=u>>1, ch=u&1.
    const float4* ptrs[3];
    #pragma unroll
    for (int t = 0; t < 3; t++) {
        int u  = gw * 3 + t;
        int rid = u >> 1, ch = u & 1;
        int n = rid / 12, kk = rid % 12;
        const float* base;
        if (kk < 3)      base = w3 + (size_t)(n * 3 + kk) * 2048;
        else if (kk < 7) base = w4 + (size_t)(n * 4 + (kk - 3)) * 2048;
        else             base = w5 + (size_t)(n * 5 + (kk - 7)) * 2048;
        ptrs[t] = (const float4*)base + ch * 256;   // half selected by ch
    }

    // Prefetch batch 0 (unit 0, first half-of-half) before staging smem.
    float4 bufA[4], bufB[4];
    #pragma unroll
    for (int j = 0; j < 4; j++) bufA[j] = ptrs[0][lane + 32 * j];

    // Stage full We + be (2560 float4, 10 per thread).
    const float4* We4 = (const float4*)We;
    const float4* be4 = (const float4*)be;
    #pragma unroll
    for (int i = 0; i < 8; i++) sW4[tid + 256 * i] = We4[tid + 256 * i];
    sW4[2048 + tid]       = be4[tid];
    sW4[2048 + 256 + tid] = be4[256 + tid];
    __syncthreads();

    float acc[5] = {0.f, 0.f, 0.f, 0.f, 0.f};

    // 6 batches: s=0..5; t=s>>1 (unit), h=s&1 (128-float4 sub-batch).
    #pragma unroll
    for (int s = 0; s < 6; s++) {
        float4* cur = (s & 1) ? bufB : bufA;
        float4* nxt = (s & 1) ? bufA : bufB;
        if (s < 5) {
            const float4* p = ptrs[(s + 1) >> 1];
            const int o = ((s + 1) & 1) * 128;
            #pragma unroll
            for (int j = 0; j < 4; j++) nxt[j] = p[o + lane + 32 * j];
        }

        const int u   = gw * 3 + (s >> 1);
        const int off = (u & 1) * 256 + (s & 1) * 128;
        #pragma unroll
        for (int j = 0; j < 4; j++) {
            const int l = off + lane + 32 * j;
            #pragma unroll
            for (int d = 0; d < 5; d++) {
                float4 sv = sW4[d * 512 + l];
                acc[d] += cur[j].x * sv.x + cur[j].y * sv.y
                        + cur[j].z * sv.z + cur[j].w * sv.w;
            }
        }

        if (s & 1) {   // end of unit: reduce, store, reset (overlaps next prefetch)
            const int rid = u >> 1, ch = u & 1;
            #pragma unroll
            for (int d = 0; d < 5; d++) {
                float a = acc[d];
                #pragma unroll
                for (int w = 16; w > 0; w >>= 1)
                    a += __shfl_down_sync(0xffffffffu, a, w);
                if (lane == 0) g_WeFp[ch * 5 * NKK + d * NKK + rid] = a;
                acc[d] = 0.f;
            }
        }
    }
}

// ---------------------------------------------------------------------------
// K2: 256 blocks = 8 c x 32 n-chunks(8 each); 128 threads (thread = cls).
// ---------------------------------------------------------------------------
__global__ void k2_v(const float* __restrict__ LUT, const float* __restrict__ W2)
{
    __shared__ float sr[96 * 16];
    __shared__ float sLUT[64];
    const int tid = threadIdx.x;     // 128
    const int c  = blockIdx.x >> 5;
    const int n0 = (blockIdx.x & 31) * 8;

    if (tid < 64) sLUT[tid] = LUT[c * 64 + tid];
    __syncthreads();

    if (tid < 96) {
        int nl = tid / 12, kk = tid % 12;
        int nkk = (n0 + nl) * 12 + kk;
        float v0 = g_WeFp[nkk]           + g_WeFp[5 * NKK + nkk];
        float v1 = g_WeFp[NKK + nkk]     + g_WeFp[6 * NKK + nkk];
        float v2 = g_WeFp[2 * NKK + nkk] + g_WeFp[7 * NKK + nkk];
        float v3 = g_WeFp[3 * NKK + nkk] + g_WeFp[8 * NKK + nkk];
        float v4 = g_WeFp[4 * NKK + nkk] + g_WeFp[9 * NKK + nkk];
        #pragma unroll
        for (int j = 0; j < 16; j++) {
            float r = sLUT[j * 4] * v0 + sLUT[j * 4 + 1] * v1 +
                      sLUT[j * 4 + 2] * v2 + sLUT[j * 4 + 3] * v3 + v4;
            sr[tid * 16 + j] = fmaxf(r, 0.f);
        }
    }
    __syncthreads();

    if (tid < NCLS) {
        const int cls = tid;
        float vac[16];
        #pragma unroll
        for (int j = 0; j < 16; j++) vac[j] = 0.f;

        #pragma unroll
        for (int K = 3; K <= 5; K++) {
            const int off = (K == 3) ? 0 : ((K == 4) ? 1536 : 2816);
            const int P   = 9 - K;
            const int kk0 = (K == 3) ? 0 : ((K == 4) ? 3 : 7);
            #pragma unroll
            for (int k = 0; k < 5; k++) {
                if (k >= K) break;
                int p = c - k;
                if (p < 0 || p > P - 1) continue;
                int kk = kk0 + k;
                #pragma unroll
                for (int nl = 0; nl < 8; nl++) {
                    int feat = off + (n0 + nl) * P + p;
                    float w2 = W2[feat * NCLS + cls];
                    const float4* r4 = (const float4*)&sr[(nl * 12 + kk) * 16];
                    float4 a = r4[0], b = r4[1], cc = r4[2], d = r4[3];
                    vac[0]  += a.x * w2;  vac[1]  += a.y * w2;
                    vac[2]  += a.z * w2;  vac[3]  += a.w * w2;
                    vac[4]  += b.x * w2;  vac[5]  += b.y * w2;
                    vac[6]  += b.z * w2;  vac[7]  += b.w * w2;
                    vac[8]  += cc.x * w2; vac[9]  += cc.y * w2;
                    vac[10] += cc.z * w2; vac[11] += cc.w * w2;
                    vac[12] += d.x * w2;  vac[13] += d.y * w2;
                    vac[14] += d.z * w2;  vac[15] += d.w * w2;
                }
            }
        }
        #pragma unroll
        for (int j = 0; j < 16; j++)
            atomicAdd(&g_V[(c * 16 + j) * NCLS + cls], vac[j]);
    }
}

// ---------------------------------------------------------------------------
// K3: one warp per b. Lane = 4*c + q (see round 5).
// ---------------------------------------------------------------------------
__global__ void k3_main(const void* __restrict__ xraw,
                        const float* __restrict__ len_emb,
                        const float* __restrict__ ipd_emb,
                        const float* __restrict__ W1, const float* __restrict__ b1,
                        const float* __restrict__ S,  const float* __restrict__ T,
                        const float* __restrict__ H,  const float* __restrict__ b2,
                        float* __restrict__ out)
{
    __shared__ float sW1[128], sb1[4], sS[480], sT[120], sH[240], sb2[NCLS];
    const int tid = threadIdx.x;
    if (tid < 128) sW1[tid] = W1[tid];
    if (tid < 4)   sb1[tid] = b1[tid];
    for (int i = tid; i < 480; i += 256) sS[i] = S[i];
    if (tid < 120) sT[tid] = T[tid];
    if (tid < 240) sH[tid] = H[tid];
    if (tid < NCLS) sb2[tid] = b2[tid];
    __syncthreads();

    const int warp = tid >> 5, lane = tid & 31;
    const int b = blockIdx.x * 8 + warp;
    const int is64 = g_x64;

    const int c = lane >> 2;
    const int q = lane & 3;

    int i0, i1;
    if (is64) {
        const long long* xp = (const long long*)xraw;
        i0 = (int)xp[((size_t)b * 8 + c) * 2];
        i1 = (int)xp[((size_t)b * 8 + c) * 2 + 1];
    } else {
        const int* xp = (const int*)xraw;
        i0 = xp[((size_t)b * 8 + c) * 2];
        i1 = xp[((size_t)b * 8 + c) * 2 + 1];
    }

    float4 vl = ((const float4*)(len_emb + (size_t)i0 * 16))[q];
    float4 vi = ((const float4*)(ipd_emb + (size_t)i1 * 16))[q];

    float h4[4] = {0.f, 0.f, 0.f, 0.f};
    {
        const float lv[4] = {vl.x, vl.y, vl.z, vl.w};
        const float iv[4] = {vi.x, vi.y, vi.z, vi.w};
        #pragma unroll
        for (int s = 0; s < 4; s++) {
            const int il = q * 4 + s;
            const int ii = 16 + q * 4 + s;
            #pragma unroll
            for (int d = 0; d < 4; d++) {
                h4[d] += lv[s] * sW1[il * 4 + d];
                h4[d] += iv[s] * sW1[ii * 4 + d];
            }
        }
    }
    #pragma unroll
    for (int d = 0; d < 4; d++) {
        h4[d] += __shfl_xor_sync(0xffffffffu, h4[d], 1);
        h4[d] += __shfl_xor_sync(0xffffffffu, h4[d], 2);
        h4[d] += sb1[d];
    }

    float m16[16];
    #pragma unroll
    for (int j = 0; j < 16; j++) m16[j] = 0.f;

    #pragma unroll
    for (int kq = 0; kq < 4; kq++) {
        const int k = q + kq * 4;
        if (k < 15) {
            float a = 0.f;
            #pragma unroll
            for (int d = 0; d < 4; d++) a += h4[d] * sS[(c * 4 + d) * 15 + k];
            float m = (a - sT[c * 15 + k]) - 1e-4f;
            float sgn = (m > 0.f) ? 1.f : ((m < 0.f) ? -1.f : 0.f);
            #pragma unroll
            for (int j = 0; j < 16; j++) m16[j] += sgn * sH[k * 16 + j];
        }
    }
    #pragma unroll
    for (int j = 0; j < 16; j++) {
        m16[j] += __shfl_xor_sync(0xffffffffu, m16[j], 1);
        m16[j] += __shfl_xor_sync(0xffffffffu, m16[j], 2);
    }

    int idx = 0;
    {
        float bm = m16[0];
        #pragma unroll
        for (int j = 1; j < 16; j++)
            if (m16[j] > bm) { bm = m16[j]; idx = j; }
    }

    int vrow[8];
    #pragma unroll
    for (int h = 0; h < 8; h++) {
        int ih = __shfl_sync(0xffffffffu, idx, h * 4);
        vrow[h] = (h * 16 + ih) * NCLS;
    }

    float lg[4];
    #pragma unroll
    for (int t = 0; t < 4; t++) {
        int cls = lane + 32 * t;
        if (cls < NCLS) {
            float v = sb2[cls];
            #pragma unroll
            for (int h = 0; h < 8; h++) v += g_V[vrow[h] + cls];
            lg[t] = v;
        } else {
            lg[t] = -INFINITY;
        }
    }

    float M = fmaxf(fmaxf(lg[0], lg[1]), fmaxf(lg[2], lg[3]));
    #pragma unroll
    for (int off = 16; off > 0; off >>= 1)
        M = fmaxf(M, __shfl_xor_sync(0xffffffffu, M, off));

    float ss = 0.f;
    #pragma unroll
    for (int t = 0; t < 4; t++) ss += expf(lg[t] - M);
    #pragma unroll
    for (int off = 16; off > 0; off >>= 1)
        ss += __shfl_xor_sync(0xffffffffu, ss, off);

    float lse = M + logf(ss);
    #pragma unroll
    for (int t = 0; t < 4; t++) {
        int cls = lane + 32 * t;
        if (cls < NCLS) out[(size_t)b * NCLS + cls] = lg[t] - lse;
    }
}

// ---------------------------------------------------------------------------
extern "C" void kernel_launch(void* const* d_in, const int* in_sizes, int n_in,
                              void* d_out, int out_size)
{
    (void)in_sizes; (void)n_in; (void)out_size;
    const void*  x       = d_in[0];
    const float* len_emb = (const float*)d_in[1];
    const float* ipd_emb = (const float*)d_in[2];
    const float* W1      = (const float*)d_in[3];
    const float* b1      = (const float*)d_in[4];
    const float* We      = (const float*)d_in[5];
    const float* be      = (const float*)d_in[6];
    const float* w3      = (const float*)d_in[7];
    const float* w4      = (const float*)d_in[8];
    const float* w5      = (const float*)d_in[9];
    const float* W2      = (const float*)d_in[10];
    const float* b2      = (const float*)d_in[11];
    const float* S       = (const float*)d_in[12];
    const float* H       = (const float*)d_in[13];
    const float* T       = (const float*)d_in[14];
    const float* LUT     = (const float*)d_in[15];
    float* out = (float*)d_out;

    k1_wef<<<256, 256>>>(We, be, w3, w4, w5, x);
    k2_v<<<256, 128>>>(LUT, W2);
    k3_main<<<512, 256>>>(x, len_emb, ipd_emb, W1, b1, S, T, H, b2, out);
}

// round 8
// speedup vs baseline: 1.4778x; 1.0864x over previous
#include <cuda_runtime.h>
#include <math.h>

// ---------------------------------------------------------------------------
// Problem constants
//  B=4096, SEQ=C=8, D=4, L=2048, NK=256, NCLS=100
//  filters: w3 (256,3,2048), w4 (256,4,2048), w5 (256,5,2048) -> 3072 rows
// ---------------------------------------------------------------------------

#define NKK 3072
#define NCLS 100

__device__ float g_WeFp[2 * 5 * NKK]; // [chunk][d][nkk]; d=4 holds be-projection
__device__ float g_V[8 * 16 * NCLS];
__device__ int   g_x64;

// ---------------------------------------------------------------------------
// K1: WeFp[ch][d][nkk] = sum_{l in half ch} {We[d,:],be}[l] * w_row[nkk][l]
//     Warp owns 4 rows x one 1024-float L-half -> LDS traffic only 1.25x DRAM.
//     384 blocks x 128 threads (1536 warps, ~all co-resident), depth-1
//     prefetch of 4 independent LDG.128 across 8 iterations. Reg-capped.
// ---------------------------------------------------------------------------
__global__ void __launch_bounds__(128, 4)
k1_wef(const float* __restrict__ We, const float* __restrict__ be,
       const float* __restrict__ w3, const float* __restrict__ w4,
       const float* __restrict__ w5, const void* __restrict__ xraw)
{
    __shared__ float4 sW4[5 * 256];   // [d][l4 within half]  (20 KB)
    const int tid = threadIdx.x;

    // Parallel dtype detect: warp 0 of block 0, one memory round trip.
    if (blockIdx.x == 0 && tid < 32) {
        const int* xi = (const int*)xraw;
        int any = 0;
        #pragma unroll
        for (int j = 0; j < 4; j++) any |= xi[1 + 2 * (tid + 32 * j)];
        int anyw = __any_sync(0xffffffffu, any != 0);
        if (tid == 0) g_x64 = anyw ? 0 : 1;
    }
    {
        int gz = blockIdx.x * 128 + tid;
        if (gz < 8 * 16 * NCLS) g_V[gz] = 0.f;
    }

    const int lane = tid & 31;
    const int warp = tid >> 5;
    const int grp  = blockIdx.x >> 1;     // 0..191 (16 rows each)
    const int ch   = blockIdx.x & 1;      // L-half
    const int r0   = grp * 16 + warp * 4; // 4 rows per warp

    const float4* rp[4];
    #pragma unroll
    for (int r = 0; r < 4; r++) {
        int rid = r0 + r;
        int n = rid / 12, kk = rid % 12;
        const float* base;
        if (kk < 3)      base = w3 + (size_t)(n * 3 + kk) * 2048;
        else if (kk < 7) base = w4 + (size_t)(n * 4 + (kk - 3)) * 2048;
        else             base = w5 + (size_t)(n * 5 + (kk - 7)) * 2048;
        rp[r] = (const float4*)base + ch * 256;
    }

    // Prefetch iteration 0 (4 independent LDG.128) before staging smem.
    float4 bufA[4], bufB[4];
    #pragma unroll
    for (int r = 0; r < 4; r++) bufA[r] = rp[r][lane];

    // Stage the We/be half: 128 threads x 10 float4.
    const float4* We4 = (const float4*)We;
    const float4* be4 = (const float4*)be;
    #pragma unroll
    for (int i = 0; i < 2; i++) {
        const int p = tid + 128 * i;
        sW4[p]        = We4[ch * 256 + p];
        sW4[256 + p]  = We4[512 + ch * 256 + p];
        sW4[512 + p]  = We4[1024 + ch * 256 + p];
        sW4[768 + p]  = We4[1536 + ch * 256 + p];
        sW4[1024 + p] = be4[ch * 256 + p];
    }
    __syncthreads();

    float acc[4][5];
    #pragma unroll
    for (int r = 0; r < 4; r++)
        #pragma unroll
        for (int d = 0; d < 5; d++) acc[r][d] = 0.f;

    #pragma unroll
    for (int i = 0; i < 8; i++) {
        float4* cur = (i & 1) ? bufB : bufA;
        float4* nxt = (i & 1) ? bufA : bufB;
        if (i < 7) {
            const int o = (i + 1) * 32 + lane;
            #pragma unroll
            for (int r = 0; r < 4; r++) nxt[r] = rp[r][o];
        }
        const int l = i * 32 + lane;
        #pragma unroll
        for (int d = 0; d < 5; d++) {
            float4 s = sW4[d * 256 + l];
            #pragma unroll
            for (int r = 0; r < 4; r++)
                acc[r][d] += cur[r].x * s.x + cur[r].y * s.y
                           + cur[r].z * s.z + cur[r].w * s.w;
        }
    }

    #pragma unroll
    for (int r = 0; r < 4; r++)
        #pragma unroll
        for (int d = 0; d < 5; d++) {
            float a = acc[r][d];
            #pragma unroll
            for (int w = 16; w > 0; w >>= 1)
                a += __shfl_down_sync(0xffffffffu, a, w);
            if (lane == 0)
                g_WeFp[ch * 5 * NKK + d * NKK + (r0 + r)] = a;
        }
}

// ---------------------------------------------------------------------------
// K2: 256 blocks = 8 c x 32 n-chunks(8 each); 128 threads (thread = cls).
// ---------------------------------------------------------------------------
__global__ void k2_v(const float* __restrict__ LUT, const float* __restrict__ W2)
{
    __shared__ float sr[96 * 16];
    __shared__ float sLUT[64];
    const int tid = threadIdx.x;     // 128
    const int c  = blockIdx.x >> 5;
    const int n0 = (blockIdx.x & 31) * 8;

    if (tid < 64) sLUT[tid] = LUT[c * 64 + tid];
    __syncthreads();

    if (tid < 96) {
        int nl = tid / 12, kk = tid % 12;
        int nkk = (n0 + nl) * 12 + kk;
        float v0 = g_WeFp[nkk]           + g_WeFp[5 * NKK + nkk];
        float v1 = g_WeFp[NKK + nkk]     + g_WeFp[6 * NKK + nkk];
        float v2 = g_WeFp[2 * NKK + nkk] + g_WeFp[7 * NKK + nkk];
        float v3 = g_WeFp[3 * NKK + nkk] + g_WeFp[8 * NKK + nkk];
        float v4 = g_WeFp[4 * NKK + nkk] + g_WeFp[9 * NKK + nkk];
        #pragma unroll
        for (int j = 0; j < 16; j++) {
            float r = sLUT[j * 4] * v0 + sLUT[j * 4 + 1] * v1 +
                      sLUT[j * 4 + 2] * v2 + sLUT[j * 4 + 3] * v3 + v4;
            sr[tid * 16 + j] = fmaxf(r, 0.f);
        }
    }
    __syncthreads();

    if (tid < NCLS) {
        const int cls = tid;
        float vac[16];
        #pragma unroll
        for (int j = 0; j < 16; j++) vac[j] = 0.f;

        #pragma unroll
        for (int K = 3; K <= 5; K++) {
            const int off = (K == 3) ? 0 : ((K == 4) ? 1536 : 2816);
            const int P   = 9 - K;
            const int kk0 = (K == 3) ? 0 : ((K == 4) ? 3 : 7);
            #pragma unroll
            for (int k = 0; k < 5; k++) {
                if (k >= K) break;
                int p = c - k;
                if (p < 0 || p > P - 1) continue;
                int kk = kk0 + k;
                #pragma unroll
                for (int nl = 0; nl < 8; nl++) {
                    int feat = off + (n0 + nl) * P + p;
                    float w2 = W2[feat * NCLS + cls];
                    const float4* r4 = (const float4*)&sr[(nl * 12 + kk) * 16];
                    float4 a = r4[0], b = r4[1], cc = r4[2], d = r4[3];
                    vac[0]  += a.x * w2;  vac[1]  += a.y * w2;
                    vac[2]  += a.z * w2;  vac[3]  += a.w * w2;
                    vac[4]  += b.x * w2;  vac[5]  += b.y * w2;
                    vac[6]  += b.z * w2;  vac[7]  += b.w * w2;
                    vac[8]  += cc.x * w2; vac[9]  += cc.y * w2;
                    vac[10] += cc.z * w2; vac[11] += cc.w * w2;
                    vac[12] += d.x * w2;  vac[13] += d.y * w2;
                    vac[14] += d.z * w2;  vac[15] += d.w * w2;
                }
            }
        }
        #pragma unroll
        for (int j = 0; j < 16; j++)
            atomicAdd(&g_V[(c * 16 + j) * NCLS + cls], vac[j]);
    }
}

// ---------------------------------------------------------------------------
// K3: one warp per b. Lane = 4*c + q (see round 5).
// ---------------------------------------------------------------------------
__global__ void k3_main(const void* __restrict__ xraw,
                        const float* __restrict__ len_emb,
                        const float* __restrict__ ipd_emb,
                        const float* __restrict__ W1, const float* __restrict__ b1,
                        const float* __restrict__ S,  const float* __restrict__ T,
                        const float* __restrict__ H,  const float* __restrict__ b2,
                        float* __restrict__ out)
{
    __shared__ float sW1[128], sb1[4], sS[480], sT[120], sH[240], sb2[NCLS];
    const int tid = threadIdx.x;
    if (tid < 128) sW1[tid] = W1[tid];
    if (tid < 4)   sb1[tid] = b1[tid];
    for (int i = tid; i < 480; i += 256) sS[i] = S[i];
    if (tid < 120) sT[tid] = T[tid];
    if (tid < 240) sH[tid] = H[tid];
    if (tid < NCLS) sb2[tid] = b2[tid];
    __syncthreads();

    const int warp = tid >> 5, lane = tid & 31;
    const int b = blockIdx.x * 8 + warp;
    const int is64 = g_x64;

    const int c = lane >> 2;
    const int q = lane & 3;

    int i0, i1;
    if (is64) {
        const long long* xp = (const long long*)xraw;
        i0 = (int)xp[((size_t)b * 8 + c) * 2];
        i1 = (int)xp[((size_t)b * 8 + c) * 2 + 1];
    } else {
        const int* xp = (const int*)xraw;
        i0 = xp[((size_t)b * 8 + c) * 2];
        i1 = xp[((size_t)b * 8 + c) * 2 + 1];
    }

    float4 vl = ((const float4*)(len_emb + (size_t)i0 * 16))[q];
    float4 vi = ((const float4*)(ipd_emb + (size_t)i1 * 16))[q];

    float h4[4] = {0.f, 0.f, 0.f, 0.f};
    {
        const float lv[4] = {vl.x, vl.y, vl.z, vl.w};
        const float iv[4] = {vi.x, vi.y, vi.z, vi.w};
        #pragma unroll
        for (int s = 0; s < 4; s++) {
            const int il = q * 4 + s;
            const int ii = 16 + q * 4 + s;
            #pragma unroll
            for (int d = 0; d < 4; d++) {
                h4[d] += lv[s] * sW1[il * 4 + d];
                h4[d] += iv[s] * sW1[ii * 4 + d];
            }
        }
    }
    #pragma unroll
    for (int d = 0; d < 4; d++) {
        h4[d] += __shfl_xor_sync(0xffffffffu, h4[d], 1);
        h4[d] += __shfl_xor_sync(0xffffffffu, h4[d], 2);
        h4[d] += sb1[d];
    }

    float m16[16];
    #pragma unroll
    for (int j = 0; j < 16; j++) m16[j] = 0.f;

    #pragma unroll
    for (int kq = 0; kq < 4; kq++) {
        const int k = q + kq * 4;
        if (k < 15) {
            float a = 0.f;
            #pragma unroll
            for (int d = 0; d < 4; d++) a += h4[d] * sS[(c * 4 + d) * 15 + k];
            float m = (a - sT[c * 15 + k]) - 1e-4f;
            float sgn = (m > 0.f) ? 1.f : ((m < 0.f) ? -1.f : 0.f);
            #pragma unroll
            for (int j = 0; j < 16; j++) m16[j] += sgn * sH[k * 16 + j];
        }
    }
    #pragma unroll
    for (int j = 0; j < 16; j++) {
        m16[j] += __shfl_xor_sync(0xffffffffu, m16[j], 1);
        m16[j] += __shfl_xor_sync(0xffffffffu, m16[j], 2);
    }

    int idx = 0;
    {
        float bm = m16[0];
        #pragma unroll
        for (int j = 1; j < 16; j++)
            if (m16[j] > bm) { bm = m16[j]; idx = j; }
    }

    int vrow[8];
    #pragma unroll
    for (int h = 0; h < 8; h++) {
        int ih = __shfl_sync(0xffffffffu, idx, h * 4);
        vrow[h] = (h * 16 + ih) * NCLS;
    }

    float lg[4];
    #pragma unroll
    for (int t = 0; t < 4; t++) {
        int cls = lane + 32 * t;
        if (cls < NCLS) {
            float v = sb2[cls];
            #pragma unroll
            for (int h = 0; h < 8; h++) v += g_V[vrow[h] + cls];
            lg[t] = v;
        } else {
            lg[t] = -INFINITY;
        }
    }

    float M = fmaxf(fmaxf(lg[0], lg[1]), fmaxf(lg[2], lg[3]));
    #pragma unroll
    for (int off = 16; off > 0; off >>= 1)
        M = fmaxf(M, __shfl_xor_sync(0xffffffffu, M, off));

    float ss = 0.f;
    #pragma unroll
    for (int t = 0; t < 4; t++) ss += expf(lg[t] - M);
    #pragma unroll
    for (int off = 16; off > 0; off >>= 1)
        ss += __shfl_xor_sync(0xffffffffu, ss, off);

    float lse = M + logf(ss);
    #pragma unroll
    for (int t = 0; t < 4; t++) {
        int cls = lane + 32 * t;
        if (cls < NCLS) out[(size_t)b * NCLS + cls] = lg[t] - lse;
    }
}

// ---------------------------------------------------------------------------
extern "C" void kernel_launch(void* const* d_in, const int* in_sizes, int n_in,
                              void* d_out, int out_size)
{
    (void)in_sizes; (void)n_in; (void)out_size;
    const void*  x       = d_in[0];
    const float* len_emb = (const float*)d_in[1];
    const float* ipd_emb = (const float*)d_in[2];
    const float* W1      = (const float*)d_in[3];
    const float* b1      = (const float*)d_in[4];
    const float* We      = (const float*)d_in[5];
    const float* be      = (const float*)d_in[6];
    const float* w3      = (const float*)d_in[7];
    const float* w4      = (const float*)d_in[8];
    const float* w5      = (const float*)d_in[9];
    const float* W2      = (const float*)d_in[10];
    const float* b2      = (const float*)d_in[11];
    const float* S       = (const float*)d_in[12];
    const float* H       = (const float*)d_in[13];
    const float* T       = (const float*)d_in[14];
    const float* LUT     = (const float*)d_in[15];
    float* out = (float*)d_out;

    k1_wef<<<384, 128>>>(We, be, w3, w4, w5, x);
    k2_v<<<256, 128>>>(LUT, W2);
    k3_main<<<512, 256>>>(x, len_emb, ipd_emb, W1, b1, S, T, H, b2, out);
}

// round 9
// speedup vs baseline: 1.5742x; 1.0652x over previous
#include <cuda_runtime.h>
#include <math.h>

// ---------------------------------------------------------------------------
// Problem constants
//  B=4096, SEQ=C=8, D=4, L=2048, NK=256, NCLS=100
//  filters: w3 (256,3,2048), w4 (256,4,2048), w5 (256,5,2048) -> 3072 rows
// ---------------------------------------------------------------------------

#define NKK 3072
#define NCLS 100

__device__ float    g_WeFp[2 * 5 * NKK]; // [chunk][d][nkk]; d=4 holds be-proj
__device__ float    g_V[8 * 16 * NCLS];
__device__ unsigned g_code[4096];        // packed idx: 8 positions x 4 bits

// ---------------------------------------------------------------------------
// K1: (a) WeFp[ch][d][nkk] streaming GEMV (DRAM-bound, as round 8), plus
//     (b) hidden tail work: per-warp computation of the 8 argmax codes per
//         batch row (independent of (a); rides under the memory stalls).
//     384 blocks x 128 threads; warp owns 4 rows x one 1024-float L-half.
// ---------------------------------------------------------------------------
__global__ void __launch_bounds__(128, 4)
k1_wef(const float* __restrict__ We, const float* __restrict__ be,
       const float* __restrict__ w3, const float* __restrict__ w4,
       const float* __restrict__ w5, const void* __restrict__ xraw,
       const float* __restrict__ len_emb, const float* __restrict__ ipd_emb,
       const float* __restrict__ W1, const float* __restrict__ b1,
       const float* __restrict__ S,  const float* __restrict__ T,
       const float* __restrict__ H)
{
    __shared__ float4 sW4[5 * 256];   // 20 KB
    __shared__ float sW1[128], sb1[4], sS[480], sT[120], sH[240];
    const int tid = threadIdx.x;

    {
        int gz = blockIdx.x * 128 + tid;
        if (gz < 8 * 16 * NCLS) g_V[gz] = 0.f;
    }

    const int lane = tid & 31;
    const int warp = tid >> 5;
    const int grp  = blockIdx.x >> 1;
    const int ch   = blockIdx.x & 1;
    const int r0   = grp * 16 + warp * 4;

    const float4* rp[4];
    #pragma unroll
    for (int r = 0; r < 4; r++) {
        int rid = r0 + r;
        int n = rid / 12, kk = rid % 12;
        const float* base;
        if (kk < 3)      base = w3 + (size_t)(n * 3 + kk) * 2048;
        else if (kk < 7) base = w4 + (size_t)(n * 4 + (kk - 3)) * 2048;
        else             base = w5 + (size_t)(n * 5 + (kk - 7)) * 2048;
        rp[r] = (const float4*)base + ch * 256;
    }

    // Prefetch iteration 0 before staging smem.
    float4 bufA[4], bufB[4];
    #pragma unroll
    for (int r = 0; r < 4; r++) bufA[r] = rp[r][lane];

    // Stage We/be half + idx-pipeline weights.
    const float4* We4 = (const float4*)We;
    const float4* be4 = (const float4*)be;
    #pragma unroll
    for (int i = 0; i < 2; i++) {
        const int p = tid + 128 * i;
        sW4[p]        = We4[ch * 256 + p];
        sW4[256 + p]  = We4[512 + ch * 256 + p];
        sW4[512 + p]  = We4[1024 + ch * 256 + p];
        sW4[768 + p]  = We4[1536 + ch * 256 + p];
        sW4[1024 + p] = be4[ch * 256 + p];
    }
    sW1[tid] = W1[tid];
    if (tid < 4)   sb1[tid] = b1[tid];
    #pragma unroll
    for (int i = 0; i < 4; i++) {
        int p = tid + 128 * i;
        if (p < 480) sS[p] = S[p];
    }
    if (tid < 120) sT[tid] = T[tid];
    if (tid < 240) { sH[tid] = H[tid]; }
    else if (tid - 128 < 240 && tid >= 128) { /* covered above */ }
    if (tid + 128 < 240) sH[tid + 128] = H[tid + 128];
    __syncthreads();

    float acc[4][5];
    #pragma unroll
    for (int r = 0; r < 4; r++)
        #pragma unroll
        for (int d = 0; d < 5; d++) acc[r][d] = 0.f;

    #pragma unroll
    for (int i = 0; i < 8; i++) {
        float4* cur = (i & 1) ? bufB : bufA;
        float4* nxt = (i & 1) ? bufA : bufB;
        if (i < 7) {
            const int o = (i + 1) * 32 + lane;
            #pragma unroll
            for (int r = 0; r < 4; r++) nxt[r] = rp[r][o];
        }
        const int l = i * 32 + lane;
        #pragma unroll
        for (int d = 0; d < 5; d++) {
            float4 s = sW4[d * 256 + l];
            #pragma unroll
            for (int r = 0; r < 4; r++)
                acc[r][d] += cur[r].x * s.x + cur[r].y * s.y
                           + cur[r].z * s.z + cur[r].w * s.w;
        }
    }

    #pragma unroll
    for (int r = 0; r < 4; r++)
        #pragma unroll
        for (int d = 0; d < 5; d++) {
            float a = acc[r][d];
            #pragma unroll
            for (int w = 16; w > 0; w >>= 1)
                a += __shfl_down_sync(0xffffffffu, a, w);
            if (lane == 0)
                g_WeFp[ch * 5 * NKK + d * NKK + (r0 + r)] = a;
        }

    // ------------------- idx tail work (independent of above) ---------------
    // Per-warp dtype detect: int64 layout -> first 128 odd words all zero.
    const int* xi = (const int*)xraw;
    int any = 0;
    #pragma unroll
    for (int j = 0; j < 4; j++) any |= xi[1 + 2 * (lane + 32 * j)];
    const int is64 = __any_sync(0xffffffffu, any != 0) ? 0 : 1;

    const int gw = blockIdx.x * 4 + warp;   // 0..1535
    const int c  = lane >> 2;
    const int q  = lane & 3;

    #pragma unroll
    for (int t = 0; t < 3; t++) {
        const int b = gw + 1536 * t;
        if (b < 4096) {
            int i0, i1;
            if (is64) {
                const long long* xp = (const long long*)xraw;
                i0 = (int)xp[((size_t)b * 8 + c) * 2];
                i1 = (int)xp[((size_t)b * 8 + c) * 2 + 1];
            } else {
                const int* xp = (const int*)xraw;
                i0 = xp[((size_t)b * 8 + c) * 2];
                i1 = xp[((size_t)b * 8 + c) * 2 + 1];
            }

            float4 vl = ((const float4*)(len_emb + (size_t)i0 * 16))[q];
            float4 vi = ((const float4*)(ipd_emb + (size_t)i1 * 16))[q];

            float h4[4] = {0.f, 0.f, 0.f, 0.f};
            {
                const float lv[4] = {vl.x, vl.y, vl.z, vl.w};
                const float iv[4] = {vi.x, vi.y, vi.z, vi.w};
                #pragma unroll
                for (int s = 0; s < 4; s++) {
                    const int il = q * 4 + s;
                    const int ii = 16 + q * 4 + s;
                    #pragma unroll
                    for (int d = 0; d < 4; d++) {
                        h4[d] += lv[s] * sW1[il * 4 + d];
                        h4[d] += iv[s] * sW1[ii * 4 + d];
                    }
                }
            }
            #pragma unroll
            for (int d = 0; d < 4; d++) {
                h4[d] += __shfl_xor_sync(0xffffffffu, h4[d], 1);
                h4[d] += __shfl_xor_sync(0xffffffffu, h4[d], 2);
                h4[d] += sb1[d];
            }

            float m16[16];
            #pragma unroll
            for (int j = 0; j < 16; j++) m16[j] = 0.f;

            #pragma unroll
            for (int kq = 0; kq < 4; kq++) {
                const int k = q + kq * 4;
                if (k < 15) {
                    float a = 0.f;
                    #pragma unroll
                    for (int d = 0; d < 4; d++) a += h4[d] * sS[(c * 4 + d) * 15 + k];
                    float m = (a - sT[c * 15 + k]) - 1e-4f;
                    float sgn = (m > 0.f) ? 1.f : ((m < 0.f) ? -1.f : 0.f);
                    #pragma unroll
                    for (int j = 0; j < 16; j++) m16[j] += sgn * sH[k * 16 + j];
                }
            }
            #pragma unroll
            for (int j = 0; j < 16; j++) {
                m16[j] += __shfl_xor_sync(0xffffffffu, m16[j], 1);
                m16[j] += __shfl_xor_sync(0xffffffffu, m16[j], 2);
            }

            int idx = 0;
            {
                float bm = m16[0];
                #pragma unroll
                for (int j = 1; j < 16; j++)
                    if (m16[j] > bm) { bm = m16[j]; idx = j; }   // first-max
            }

            unsigned code = 0;
            #pragma unroll
            for (int h = 0; h < 8; h++)
                code |= (unsigned)(__shfl_sync(0xffffffffu, idx, h * 4) & 15) << (4 * h);
            if (lane == 0) g_code[b] = code;
        }
    }
}

// ---------------------------------------------------------------------------
// K2: 256 blocks = 8 c x 32 n-chunks(8 each); 128 threads (thread = cls).
// ---------------------------------------------------------------------------
__global__ void k2_v(const float* __restrict__ LUT, const float* __restrict__ W2)
{
    __shared__ float sr[96 * 16];
    __shared__ float sLUT[64];
    const int tid = threadIdx.x;     // 128
    const int c  = blockIdx.x >> 5;
    const int n0 = (blockIdx.x & 31) * 8;

    if (tid < 64) sLUT[tid] = LUT[c * 64 + tid];
    __syncthreads();

    if (tid < 96) {
        int nl = tid / 12, kk = tid % 12;
        int nkk = (n0 + nl) * 12 + kk;
        float v0 = g_WeFp[nkk]           + g_WeFp[5 * NKK + nkk];
        float v1 = g_WeFp[NKK + nkk]     + g_WeFp[6 * NKK + nkk];
        float v2 = g_WeFp[2 * NKK + nkk] + g_WeFp[7 * NKK + nkk];
        float v3 = g_WeFp[3 * NKK + nkk] + g_WeFp[8 * NKK + nkk];
        float v4 = g_WeFp[4 * NKK + nkk] + g_WeFp[9 * NKK + nkk];
        #pragma unroll
        for (int j = 0; j < 16; j++) {
            float r = sLUT[j * 4] * v0 + sLUT[j * 4 + 1] * v1 +
                      sLUT[j * 4 + 2] * v2 + sLUT[j * 4 + 3] * v3 + v4;
            sr[tid * 16 + j] = fmaxf(r, 0.f);
        }
    }
    __syncthreads();

    if (tid < NCLS) {
        const int cls = tid;
        float vac[16];
        #pragma unroll
        for (int j = 0; j < 16; j++) vac[j] = 0.f;

        #pragma unroll
        for (int K = 3; K <= 5; K++) {
            const int off = (K == 3) ? 0 : ((K == 4) ? 1536 : 2816);
            const int P   = 9 - K;
            const int kk0 = (K == 3) ? 0 : ((K == 4) ? 3 : 7);
            #pragma unroll
            for (int k = 0; k < 5; k++) {
                if (k >= K) break;
                int p = c - k;
                if (p < 0 || p > P - 1) continue;
                int kk = kk0 + k;
                #pragma unroll
                for (int nl = 0; nl < 8; nl++) {
                    int feat = off + (n0 + nl) * P + p;
                    float w2 = W2[feat * NCLS + cls];
                    const float4* r4 = (const float4*)&sr[(nl * 12 + kk) * 16];
                    float4 a = r4[0], b = r4[1], cc = r4[2], d = r4[3];
                    vac[0]  += a.x * w2;  vac[1]  += a.y * w2;
                    vac[2]  += a.z * w2;  vac[3]  += a.w * w2;
                    vac[4]  += b.x * w2;  vac[5]  += b.y * w2;
                    vac[6]  += b.z * w2;  vac[7]  += b.w * w2;
                    vac[8]  += cc.x * w2; vac[9]  += cc.y * w2;
                    vac[10] += cc.z * w2; vac[11] += cc.w * w2;
                    vac[12] += d.x * w2;  vac[13] += d.y * w2;
                    vac[14] += d.z * w2;  vac[15] += d.w * w2;
                }
            }
        }
        #pragma unroll
        for (int j = 0; j < 16; j++)
            atomicAdd(&g_V[(c * 16 + j) * NCLS + cls], vac[j]);
    }
}

// ---------------------------------------------------------------------------
// K3: pure gather + log_softmax. One warp per b; code unpack -> 8 V rows.
// ---------------------------------------------------------------------------
__global__ void k3_main(const float* __restrict__ b2, float* __restrict__ out)
{
    __shared__ float sb2[NCLS];
    const int tid = threadIdx.x;
    if (tid < NCLS) sb2[tid] = b2[tid];
    __syncthreads();

    const int warp = tid >> 5, lane = tid & 31;
    const int b = blockIdx.x * 8 + warp;

    const unsigned code = g_code[b];
    int vrow[8];
    #pragma unroll
    for (int h = 0; h < 8; h++)
        vrow[h] = (h * 16 + (int)((code >> (4 * h)) & 15u)) * NCLS;

    float lg[4];
    #pragma unroll
    for (int t = 0; t < 4; t++) {
        int cls = lane + 32 * t;
        if (cls < NCLS) {
            float v = sb2[cls];
            #pragma unroll
            for (int h = 0; h < 8; h++) v += g_V[vrow[h] + cls];
            lg[t] = v;
        } else {
            lg[t] = -INFINITY;
        }
    }

    float M = fmaxf(fmaxf(lg[0], lg[1]), fmaxf(lg[2], lg[3]));
    #pragma unroll
    for (int off = 16; off > 0; off >>= 1)
        M = fmaxf(M, __shfl_xor_sync(0xffffffffu, M, off));

    float ss = 0.f;
    #pragma unroll
    for (int t = 0; t < 4; t++) ss += expf(lg[t] - M);
    #pragma unroll
    for (int off = 16; off > 0; off >>= 1)
        ss += __shfl_xor_sync(0xffffffffu, ss, off);

    float lse = M + logf(ss);
    #pragma unroll
    for (int t = 0; t < 4; t++) {
        int cls = lane + 32 * t;
        if (cls < NCLS) out[(size_t)b * NCLS + cls] = lg[t] - lse;
    }
}

// ---------------------------------------------------------------------------
extern "C" void kernel_launch(void* const* d_in, const int* in_sizes, int n_in,
                              void* d_out, int out_size)
{
    (void)in_sizes; (void)n_in; (void)out_size;
    const void*  x       = d_in[0];
    const float* len_emb = (const float*)d_in[1];
    const float* ipd_emb = (const float*)d_in[2];
    const float* W1      = (const float*)d_in[3];
    const float* b1      = (const float*)d_in[4];
    const float* We      = (const float*)d_in[5];
    const float* be      = (const float*)d_in[6];
    const float* w3      = (const float*)d_in[7];
    const float* w4      = (const float*)d_in[8];
    const float* w5      = (const float*)d_in[9];
    const float* W2      = (const float*)d_in[10];
    const float* b2      = (const float*)d_in[11];
    const float* S       = (const float*)d_in[12];
    const float* H       = (const float*)d_in[13];
    const float* T       = (const float*)d_in[14];
    const float* LUT     = (const float*)d_in[15];
    float* out = (float*)d_out;

    k1_wef<<<384, 128>>>(We, be, w3, w4, w5, x,
                         len_emb, ipd_emb, W1, b1, S, T, H);
    k2_v<<<256, 128>>>(LUT, W2);
    k3_main<<<512, 256>>>(b2, out);
}